// round 2
// baseline (speedup 1.0000x reference)
#include <cuda_runtime.h>
#include <cstdint>

// Problem constants
#define B_   256
#define T_   127
#define K_   128
#define H_   256
#define G4_  1024        // 4*H
#define CL_  8           // cluster size (CTAs per cluster)
#define MB_  16          // batches per cluster
#define HS_  32          // hidden units per CTA (H_/CL_)

// ---------------------------------------------------------------------------
// Kernel A: alpha = softmax_k( sum_t input[b,t,k]*W_x[t] ), then
//           weight[b,t,k] = alpha[b,k]*input[b,t,k]  (written fully to d_out)
// The per-batch scalar (h@W_h + c@W_c) and fc_b cancel inside softmax.
// ---------------------------------------------------------------------------
__global__ void __launch_bounds__(128) k_alpha(const float* __restrict__ inp,
                                               const float* __restrict__ fc_w,
                                               float* __restrict__ out_w) {
    __shared__ float wx[T_];
    __shared__ float red[4];
    const int b = blockIdx.x;
    const int k = threadIdx.x;           // 0..127
    if (k < T_) wx[k] = fc_w[2 * H_ + k];
    __syncthreads();

    const float* ib = inp + (size_t)b * T_ * K_;
    float acc = 0.f;
#pragma unroll 4
    for (int t = 0; t < T_; t++) acc += ib[t * K_ + k] * wx[t];

    // block max over 128 lanes
    float m = acc;
#pragma unroll
    for (int o = 16; o; o >>= 1) m = fmaxf(m, __shfl_xor_sync(0xffffffffu, m, o));
    if ((k & 31) == 0) red[k >> 5] = m;
    __syncthreads();
    m = fmaxf(fmaxf(red[0], red[1]), fmaxf(red[2], red[3]));
    __syncthreads();

    float e = __expf(acc - m);
    float s = e;
#pragma unroll
    for (int o = 16; o; o >>= 1) s += __shfl_xor_sync(0xffffffffu, s, o);
    if ((k & 31) == 0) red[k >> 5] = s;
    __syncthreads();
    s = red[0] + red[1] + red[2] + red[3];
    const float alpha = e / s;

    float* ob = out_w + (size_t)b * T_ * K_;
#pragma unroll 4
    for (int t = 0; t < T_; t++) ob[t * K_ + k] = alpha * ib[t * K_ + k];
}

// ---------------------------------------------------------------------------
// Kernel B: persistent LSTM recurrence. Cluster of 8 CTAs; each CTA owns a
// 32-unit hidden slice with its W_ih / W_hh gate-row slices resident in SMEM
// (transposed, rows padded to 129 floats). h is exchanged per step via DSMEM.
// ---------------------------------------------------------------------------

// smem layout (floats)
#define OFF_WI   0                         // [128 k][129] (pad)
#define OFF_WH   (OFF_WI + 128 * 129)      // [256 n][129]
#define OFF_XT   (OFF_WH + 256 * 129)      // [128 k][20]  (x transposed; reused for gates)
#define OFF_HT   (OFF_XT + 128 * 20)       // [256 n][20]  (h transposed, full H)
#define OFF_CT   (OFF_HT + 256 * 20)       // [32 jl][16]  (c slice)
#define OFF_BS   (OFF_CT + 32 * 16)        // [128]        (bias slice)
#define SMEM_FLOATS (OFF_BS + 128)
#define SMEM_B_BYTES (SMEM_FLOATS * 4)     // 231424 bytes

__device__ __forceinline__ unsigned smem_u32(const void* p) {
    return (unsigned)__cvta_generic_to_shared(p);
}
__device__ __forceinline__ void st_cluster_f32(unsigned addr, unsigned rank, float v) {
    unsigned ra;
    asm volatile("mapa.shared::cluster.u32 %0, %1, %2;" : "=r"(ra) : "r"(addr), "r"(rank));
    asm volatile("st.shared::cluster.f32 [%0], %1;" :: "r"(ra), "f"(v) : "memory");
}
__device__ __forceinline__ void cluster_barrier() {
    asm volatile("barrier.cluster.arrive.aligned;" ::: "memory");
    asm volatile("barrier.cluster.wait.aligned;" ::: "memory");
}
__device__ __forceinline__ float sigm(float x) { return 1.f / (1.f + __expf(-x)); }

__global__ void __launch_bounds__(256, 1) __cluster_dims__(CL_, 1, 1)
k_lstm(const float* __restrict__ W_ih, const float* __restrict__ W_hh,
       const float* __restrict__ b_ih, const float* __restrict__ b_hh,
       const float* __restrict__ xw,   // = weight output (B,T,K), precomputed by k_alpha
       float* __restrict__ out_h) {
    extern __shared__ float sm[];
    float* Wi = sm + OFF_WI;
    float* Wh = sm + OFF_WH;
    float* xT = sm + OFF_XT;   // also gates buffer g_s after gemv
    float* hT = sm + OFF_HT;
    float* cT = sm + OFF_CT;
    float* bs = sm + OFF_BS;

    const int tid = threadIdx.x;
    unsigned rank;
    asm("mov.u32 %0, %%cluster_ctarank;" : "=r"(rank));
    const int cid = blockIdx.x / CL_;
    const int b0  = cid * MB_;

    // ---- load weight slices (transposed, gate rows gathered) ----
    // local gate-row r = q*32 + jl  ->  global row = q*256 + rank*32 + jl
    for (int idx = tid; idx < 128 * 128; idx += 256) {
        int r = idx >> 7, k = idx & 127;
        int grow = (r >> 5) * H_ + (int)rank * HS_ + (r & 31);
        Wi[k * 129 + r] = W_ih[grow * K_ + k];
    }
    for (int idx = tid; idx < 256 * 128; idx += 256) {
        int r = idx >> 8, n = idx & 255;
        int grow = (r >> 5) * H_ + (int)rank * HS_ + (r & 31);
        Wh[n * 129 + r] = W_hh[grow * H_ + n];
    }
    if (tid < 128) {
        int grow = (tid >> 5) * H_ + (int)rank * HS_ + (tid & 31);
        bs[tid] = b_ih[grow] + b_hh[grow];
    }
    for (int idx = tid; idx < 256 * 20; idx += 256) hT[idx] = 0.f;
    for (int idx = tid; idx < 32 * 16; idx += 256) cT[idx] = 0.f;
    __syncthreads();

    const int r  = tid & 127;
    const int mh = tid >> 7;          // 0 or 1 -> batch group m = mh*8 + j
    const float* xm = xT + mh * 8;
    const float* hm = hT + mh * 8;

    for (int t = 0; t < T_; t++) {
        // ---- phase 1: stage x_t (transposed) ----
#pragma unroll
        for (int i = 0; i < 8; i++) {
            int idx = tid + 256 * i;
            int m = idx >> 7, k = idx & 127;
            xT[k * 20 + m] = xw[((size_t)(b0 + m) * T_ + t) * K_ + k];
        }
        __syncthreads();

        // ---- phase 2: gemv (gates slice for 16 batches) ----
        float a0, a1, a2, a3, a4, a5, a6, a7;
        a0 = a1 = a2 = a3 = a4 = a5 = a6 = a7 = bs[r];
        {
            const float* wrow = Wi + r;
#pragma unroll 4
            for (int k = 0; k < K_; k++) {
                float w = wrow[k * 129];
                float4 xa = *reinterpret_cast<const float4*>(xm + k * 20);
                float4 xb = *reinterpret_cast<const float4*>(xm + k * 20 + 4);
                a0 += w * xa.x; a1 += w * xa.y; a2 += w * xa.z; a3 += w * xa.w;
                a4 += w * xb.x; a5 += w * xb.y; a6 += w * xb.z; a7 += w * xb.w;
            }
            wrow = Wh + r;
#pragma unroll 4
            for (int n = 0; n < H_; n++) {
                float w = wrow[n * 129];
                float4 ha = *reinterpret_cast<const float4*>(hm + n * 20);
                float4 hb = *reinterpret_cast<const float4*>(hm + n * 20 + 4);
                a0 += w * ha.x; a1 += w * ha.y; a2 += w * ha.z; a3 += w * ha.w;
                a4 += w * hb.x; a5 += w * hb.y; a6 += w * hb.z; a7 += w * hb.w;
            }
        }

        // cluster sync #1: all CTAs finished reading hT; peers may now overwrite it
        cluster_barrier();

        // ---- phase 3: write gates into xT (reused) ----
        *reinterpret_cast<float4*>(&xT[r * 20 + mh * 8])     = make_float4(a0, a1, a2, a3);
        *reinterpret_cast<float4*>(&xT[r * 20 + mh * 8 + 4]) = make_float4(a4, a5, a6, a7);
        __syncthreads();

        // ---- phase 4: LSTM cell for (jl, m); broadcast h slice to all peers ----
#pragma unroll
        for (int it = 0; it < 2; it++) {
            int idx = tid + 256 * it;       // 512 items: m fastest (conflict-free)
            int m  = idx & 15;
            int jl = (idx >> 4) & 31;
            float gi = xT[(jl)      * 20 + m];
            float gf = xT[(32 + jl) * 20 + m];
            float gg = xT[(64 + jl) * 20 + m];
            float go = xT[(96 + jl) * 20 + m];
            float cp = cT[jl * 16 + m];
            float cn = sigm(gf) * cp + sigm(gi) * tanhf(gg);
            float hn = sigm(go) * tanhf(cn);
            cT[jl * 16 + m] = cn;
            unsigned la = smem_u32(&hT[((int)rank * HS_ + jl) * 20 + m]);
#pragma unroll
            for (unsigned pr = 0; pr < CL_; pr++) st_cluster_f32(la, pr, hn);
        }
        __syncthreads();

        // ---- phase 5: coalesced global write of this CTA's h slice ----
#pragma unroll
        for (int it = 0; it < 2; it++) {
            int idx = tid + 256 * it;       // jl fastest -> 128B coalesced per m
            int jl = idx & 31;
            int m  = idx >> 5;
            float v = hT[((int)rank * HS_ + jl) * 20 + m];
            out_h[((size_t)(b0 + m) * T_ + t) * H_ + (int)rank * HS_ + jl] = v;
        }

        // cluster sync #2: all h writes (local+remote) visible before next gemv
        cluster_barrier();
    }
}

// ---------------------------------------------------------------------------
// Launch
// ---------------------------------------------------------------------------
extern "C" void kernel_launch(void* const* d_in, const int* in_sizes, int n_in,
                              void* d_out, int out_size) {
    const float* input = (const float*)d_in[0];
    const float* W_ih  = (const float*)d_in[1];
    const float* W_hh  = (const float*)d_in[2];
    const float* b_ih  = (const float*)d_in[3];
    const float* b_hh  = (const float*)d_in[4];
    const float* fc_w  = (const float*)d_in[5];
    // d_in[6] = fc_b (cancels inside softmax)

    float* out   = (float*)d_out;
    float* out_w = out;                                   // (B,T,K)
    float* out_h = out + (size_t)B_ * T_ * K_;            // (B,T,H)

    cudaFuncSetAttribute(k_lstm, cudaFuncAttributeMaxDynamicSharedMemorySize,
                         SMEM_B_BYTES);

    k_alpha<<<B_, 128>>>(input, fc_w, out_w);
    k_lstm<<<(B_ / MB_) * CL_, 256, SMEM_B_BYTES>>>(W_ih, W_hh, b_ih, b_hh,
                                                    out_w, out_h);
}

// round 3
// speedup vs baseline: 1.0612x; 1.0612x over previous
#include <cuda_runtime.h>
#include <cstdint>

// Problem constants
#define B_   256
#define T_   127
#define K_   128
#define H_   256
#define CL_  8           // cluster size (CTAs per cluster)
#define MB_  16          // batches per cluster
#define HS_  32          // hidden units per CTA (H_/CL_)
#define NT_  512         // threads per CTA

// ---------------------------------------------------------------------------
// Kernel A: alpha = softmax_k( sum_t input[b,t,k]*W_x[t] ), then
//           weight[b,t,k] = alpha[b,k]*input[b,t,k]
// (h@W_h + c@W_c and fc_b are per-row constants -> cancel inside softmax)
// ---------------------------------------------------------------------------
__global__ void __launch_bounds__(128) k_alpha(const float* __restrict__ inp,
                                               const float* __restrict__ fc_w,
                                               float* __restrict__ out_w) {
    __shared__ float wx[T_];
    __shared__ float red[4];
    const int b = blockIdx.x;
    const int k = threadIdx.x;           // 0..127
    if (k < T_) wx[k] = fc_w[2 * H_ + k];
    __syncthreads();

    const float* ib = inp + (size_t)b * T_ * K_;
    float acc = 0.f;
#pragma unroll 4
    for (int t = 0; t < T_; t++) acc += ib[t * K_ + k] * wx[t];

    float m = acc;
#pragma unroll
    for (int o = 16; o; o >>= 1) m = fmaxf(m, __shfl_xor_sync(0xffffffffu, m, o));
    if ((k & 31) == 0) red[k >> 5] = m;
    __syncthreads();
    m = fmaxf(fmaxf(red[0], red[1]), fmaxf(red[2], red[3]));
    __syncthreads();

    float e = __expf(acc - m);
    float s = e;
#pragma unroll
    for (int o = 16; o; o >>= 1) s += __shfl_xor_sync(0xffffffffu, s, o);
    if ((k & 31) == 0) red[k >> 5] = s;
    __syncthreads();
    s = red[0] + red[1] + red[2] + red[3];
    const float alpha = e / s;

    float* ob = out_w + (size_t)b * T_ * K_;
#pragma unroll 4
    for (int t = 0; t < T_; t++) ob[t * K_ + k] = alpha * ib[t * K_ + k];
}

// ---------------------------------------------------------------------------
// Kernel B: persistent LSTM recurrence (cluster of 8 CTAs, SMEM weights,
// DSMEM h-exchange). 512 threads: 128 rows x 2 batch-halves x 2 K-halves.
// ---------------------------------------------------------------------------

// smem layout (floats)
#define OFF_WI   0                         // [128 k][129]
#define OFF_WH   (OFF_WI + 128 * 129)      // [256 n][129]
#define OFF_XT   (OFF_WH + 256 * 129)      // [128 k][20] x transposed / partials / gates / h-buf
#define OFF_HT   (OFF_XT + 128 * 20)       // [256 n][20]  h transposed (full H)
#define OFF_CT   (OFF_HT + 256 * 20)       // [32 jl][16]  c slice
#define OFF_BS   (OFF_CT + 32 * 16)        // [128] bias slice
#define SMEM_FLOATS (OFF_BS + 128)
#define SMEM_B_BYTES (SMEM_FLOATS * 4)     // 231424 bytes

__device__ __forceinline__ unsigned smem_u32(const void* p) {
    return (unsigned)__cvta_generic_to_shared(p);
}
__device__ __forceinline__ unsigned mapa_rank(unsigned addr, unsigned rank) {
    unsigned ra;
    asm("mapa.shared::cluster.u32 %0, %1, %2;" : "=r"(ra) : "r"(addr), "r"(rank));
    return ra;
}
__device__ __forceinline__ void st_cluster_f32(unsigned ra, float v) {
    asm volatile("st.shared::cluster.f32 [%0], %1;" :: "r"(ra), "f"(v) : "memory");
}
__device__ __forceinline__ void cl_arrive() {
    asm volatile("barrier.cluster.arrive.aligned;" ::: "memory");
}
__device__ __forceinline__ void cl_wait() {
    asm volatile("barrier.cluster.wait.aligned;" ::: "memory");
}
__device__ __forceinline__ float sigm(float x) { return 1.f / (1.f + __expf(-x)); }
__device__ __forceinline__ float ftanh(float x) {
    return 2.f / (1.f + __expf(-2.f * x)) - 1.f;
}

__device__ __forceinline__ unsigned long long pack2(float v) {
    unsigned long long d;
    unsigned u = __float_as_uint(v);
    asm("mov.b64 %0, {%1, %1};" : "=l"(d) : "r"(u));
    return d;
}
__device__ __forceinline__ void fma2(unsigned long long& a,
                                     unsigned long long w,
                                     unsigned long long x) {
    asm("fma.rn.f32x2 %0, %1, %2, %0;" : "+l"(a) : "l"(w), "l"(x));
}
__device__ __forceinline__ float2 unpack2(unsigned long long a) {
    unsigned lo, hi;
    asm("mov.b64 {%0, %1}, %2;" : "=r"(lo), "=r"(hi) : "l"(a));
    return make_float2(__uint_as_float(lo), __uint_as_float(hi));
}

__global__ void __launch_bounds__(NT_, 1) __cluster_dims__(CL_, 1, 1)
k_lstm(const float* __restrict__ W_ih, const float* __restrict__ W_hh,
       const float* __restrict__ b_ih, const float* __restrict__ b_hh,
       const float* __restrict__ xw,   // (B,T,K) precomputed by k_alpha
       float* __restrict__ out_h) {
    extern __shared__ float sm[];
    float* Wi = sm + OFF_WI;
    float* Wh = sm + OFF_WH;
    float* xT = sm + OFF_XT;
    float* hT = sm + OFF_HT;
    float* cT = sm + OFF_CT;
    float* bs = sm + OFF_BS;

    const int tid = threadIdx.x;
    unsigned rank;
    asm("mov.u32 %0, %%cluster_ctarank;" : "=r"(rank));
    const int cid = blockIdx.x / CL_;
    const int b0  = cid * MB_;

    // ---- init: weight slices (transposed, padded 129), bias, states ----
    for (int idx = tid; idx < 128 * 128; idx += NT_) {
        int r = idx >> 7, k = idx & 127;
        int grow = (r >> 5) * H_ + (int)rank * HS_ + (r & 31);
        Wi[k * 129 + r] = W_ih[grow * K_ + k];
    }
    for (int idx = tid; idx < 256 * 128; idx += NT_) {
        int r = idx >> 8, n = idx & 255;
        int grow = (r >> 5) * H_ + (int)rank * HS_ + (r & 31);
        Wh[n * 129 + r] = W_hh[grow * H_ + n];
    }
    if (tid < 128) {
        int grow = (tid >> 5) * H_ + (int)rank * HS_ + (tid & 31);
        bs[tid] = b_ih[grow] + b_hh[grow];
    }
    for (int idx = tid; idx < 256 * 20; idx += NT_) hT[idx] = 0.f;
    if (tid < 512) cT[tid] = 0.f;
    __syncthreads();

    // ---- thread roles ----
    const int r  = tid & 127;          // gate row (local)
    const int g  = tid >> 7;           // 0..3
    const int mh = g & 1;              // batch half (8 batches)
    const int kh = g >> 1;             // K half
    const float* xm = xT + mh * 8;
    const float* hm = hT + mh * 8;
    float* gslot = xT + r * 20 + mh * 8;

    // cell-phase role
    const int cm  = tid & 15;          // batch 0..15
    const int cjl = tid >> 4;          // hidden unit 0..31
    // precompute DSMEM addresses for broadcasting h[cjl, cm] to all ranks
    unsigned hdst[CL_];
    {
        unsigned la = smem_u32(&hT[((int)rank * HS_ + cjl) * 20 + cm]);
#pragma unroll
        for (unsigned pr = 0; pr < CL_; pr++) hdst[pr] = mapa_rank(la, pr);
    }

    cl_arrive();   // pairs with first wait; also publishes our hT zero-init

    for (int t = 0; t < T_; t++) {
        // ---- stage x_t (transposed) ----
#pragma unroll
        for (int i = 0; i < 4; i++) {
            int idx = tid + NT_ * i;
            int m = idx >> 7, k = idx & 127;
            xT[k * 20 + m] = xw[((size_t)(b0 + m) * T_ + t) * K_ + k];
        }
        __syncthreads();

        cl_wait();   // peers' h writes (prev step) visible; our readers may go

        // ---- gemv: half-K reduction, 8 batch-accumulators as 4 f32x2 ----
        unsigned long long A0, A1, A2, A3;
        {
            unsigned long long binit = pack2(kh == 0 ? bs[r] : 0.f);
            A0 = A1 = A2 = A3 = binit;
        }
        {
            const float* wp = Wi + (kh * 64) * 129 + r;
            const float* xp = xm + (kh * 64) * 20;
#pragma unroll 4
            for (int kk = 0; kk < 64; kk++) {
                unsigned long long w2 = pack2(wp[kk * 129]);
                ulonglong2 xa = *reinterpret_cast<const ulonglong2*>(xp + kk * 20);
                ulonglong2 xb = *reinterpret_cast<const ulonglong2*>(xp + kk * 20 + 4);
                fma2(A0, w2, xa.x); fma2(A1, w2, xa.y);
                fma2(A2, w2, xb.x); fma2(A3, w2, xb.y);
            }
            const float* wq = Wh + (kh * 128) * 129 + r;
            const float* hp = hm + (kh * 128) * 20;
#pragma unroll 4
            for (int nn = 0; nn < 128; nn++) {
                unsigned long long w2 = pack2(wq[nn * 129]);
                ulonglong2 ha = *reinterpret_cast<const ulonglong2*>(hp + nn * 20);
                ulonglong2 hb = *reinterpret_cast<const ulonglong2*>(hp + nn * 20 + 4);
                fma2(A0, w2, ha.x); fma2(A1, w2, ha.y);
                fma2(A2, w2, hb.x); fma2(A3, w2, hb.y);
            }
        }
        float2 p0 = unpack2(A0), p1 = unpack2(A1), p2 = unpack2(A2), p3 = unpack2(A3);

        __syncthreads();   // all threads done reading xT (x) and hT
        cl_arrive();       // signal: done reading peers' h contributions

        // ---- combine K-halves: kh==1 writes partials, kh==0 reduces+stores gates
        if (kh == 1) {
            *reinterpret_cast<float4*>(gslot)     = make_float4(p0.x, p0.y, p1.x, p1.y);
            *reinterpret_cast<float4*>(gslot + 4) = make_float4(p2.x, p2.y, p3.x, p3.y);
        }
        __syncthreads();
        if (kh == 0) {
            float4 q0 = *reinterpret_cast<float4*>(gslot);
            float4 q1 = *reinterpret_cast<float4*>(gslot + 4);
            *reinterpret_cast<float4*>(gslot) =
                make_float4(p0.x + q0.x, p0.y + q0.y, p1.x + q0.z, p1.y + q0.w);
            *reinterpret_cast<float4*>(gslot + 4) =
                make_float4(p2.x + q1.x, p2.y + q1.y, p3.x + q1.z, p3.y + q1.w);
        }
        __syncthreads();

        // ---- cell: read gates -> regs ----
        float gi = xT[(cjl)      * 20 + cm];
        float gf = xT[(32 + cjl) * 20 + cm];
        float gg = xT[(64 + cjl) * 20 + cm];
        float go = xT[(96 + cjl) * 20 + cm];
        float cp = cT[cjl * 16 + cm];
        float cn = sigm(gf) * cp + sigm(gi) * ftanh(gg);
        float hn = sigm(go) * ftanh(cn);
        cT[cjl * 16 + cm] = cn;
        __syncthreads();   // gates fully consumed; xT reusable

        cl_wait();         // all CTAs done reading hT -> safe to overwrite

        // ---- publish h: local staging buffer + DSMEM broadcast ----
        xT[cjl * 17 + cm] = hn;
#pragma unroll
        for (int pr = 0; pr < CL_; pr++) st_cluster_f32(hdst[pr], hn);
        cl_arrive();       // release our h writes to peers
        __syncthreads();

        // ---- coalesced global store of this CTA's h slice ----
        {
            int jl = tid & 31;
            int m  = tid >> 5;
            float v = xT[jl * 17 + m];
            out_h[((size_t)(b0 + m) * T_ + t) * H_ + (int)rank * HS_ + jl] = v;
        }
        __syncthreads();   // protect xT buffer before next stage overwrites
    }
    cl_wait();             // pair final arrive
}

// ---------------------------------------------------------------------------
// Launch
// ---------------------------------------------------------------------------
extern "C" void kernel_launch(void* const* d_in, const int* in_sizes, int n_in,
                              void* d_out, int out_size) {
    const float* input = (const float*)d_in[0];
    const float* W_ih  = (const float*)d_in[1];
    const float* W_hh  = (const float*)d_in[2];
    const float* b_ih  = (const float*)d_in[3];
    const float* b_hh  = (const float*)d_in[4];
    const float* fc_w  = (const float*)d_in[5];
    // d_in[6] = fc_b (cancels inside softmax)

    float* out   = (float*)d_out;
    float* out_w = out;                                   // (B,T,K)
    float* out_h = out + (size_t)B_ * T_ * K_;            // (B,T,H)

    cudaFuncSetAttribute(k_lstm, cudaFuncAttributeMaxDynamicSharedMemorySize,
                         SMEM_B_BYTES);

    k_alpha<<<B_, 128>>>(input, fc_w, out_w);
    k_lstm<<<(B_ / MB_) * CL_, NT_, SMEM_B_BYTES>>>(W_ih, W_hh, b_ih, b_hh,
                                                    out_w, out_h);
}